// round 14
// baseline (speedup 1.0000x reference)
#include <cuda_runtime.h>

// EMA alpha=0.2; out[i] = e_{idx}, idx = max(len[i],1)-1.
// 64-tap trailing window (tail weight 0.8^63 ~ 8e-7 << 1e-3 threshold);
// rows with idx < 64 computed exactly from x_0.
//
// FINAL (canonical best, R1-R13): 4-lane row groups, 8 rows per warp ->
// 2048 warps, 256 CTAs of 256 threads (16 warps/SM latency-hiding knee;
// 8 w/SM regresses, 32 w/SM ties). Each lane: FOUR independent aligned
// LDG.128 (float4) covering the 64-float window (MLP=4). Window start
// aligned up to 4 (keeps s >= n-63), clamped to [0, T-64].
//
// Measured floor: bench 6.62-7.14us across identical binaries (DVFS noise
// +-0.4us dominates); ncu 5.70-6.05us. Overhead-bound: launch/ramp ~2.8us +
// dependent len->window trip (mostly L2-hit across graph replays) + drain.
// DRAM 13%, issue 12% — no throughput axis remains. All structural levers
// (warp shape, CTA shape, TAPS, body scheduling, guard elision) swept;
// none separates from noise.

#define LOG2_08  (-0.32192809488736234787f)  // log2(0.8)
#define INV08_16 (35.52713678800501f)        // 0.8^-16 = 1.25^16

__global__ void __launch_bounds__(256)
ema_last_kernel(const float* __restrict__ x,
                const int* __restrict__ valid_len,
                float* __restrict__ out,
                int B, int T)
{
    int warp = (int)((blockIdx.x * blockDim.x + threadIdx.x) >> 5);
    int lane = threadIdx.x & 31;
    int sub  = lane & 3;                 // lane within 4-lane row group
    int row  = warp * 8 + (lane >> 2);
    if (row >= B) return;

    int len = valid_len[row];
    int n   = (len > 1 ? len : 1) - 1;   // target index idx = L-1

    // Aligned window start: s in [n-63, n-60] (or 0), 4-aligned, in-row.
    int s = n - 63;
    s = (s > 0) ? ((s + 3) & ~3) : 0;
    if (s > T - 64) s = T - 64;

    const float4* p = reinterpret_cast<const float4*>(x + (size_t)row * (size_t)T + s);
    // Four independent loads issue back-to-back (MLP=4).
    float4 a = p[sub];
    float4 b = p[sub + 4];
    float4 c = p[sub + 8];
    float4 d = p[sub + 12];

    int ja = s + 4 * sub;                // global index of a.x
    int jb = ja + 16, jc = ja + 32, jd = ja + 48;

    // tap weight: 0.2 * 0.8^(n - j); seed (j==0) coefficient is 0.8^n = 5x that.
    float wa = 0.2f * exp2f((float)(n - ja) * LOG2_08);
    float wb = wa * INV08_16;
    float wc = wb * INV08_16;
    float wd = wc * INV08_16;

    float a0 = wa, a1 = wa * 1.25f, a2 = wa * 1.5625f, a3 = wa * 1.953125f;
    float b0 = wb, b1 = wb * 1.25f, b2 = wb * 1.5625f, b3 = wb * 1.953125f;
    float c0 = wc, c1 = wc * 1.25f, c2 = wc * 1.5625f, c3 = wc * 1.953125f;
    float d0 = wd, d1 = wd * 1.25f, d2 = wd * 1.5625f, d3 = wd * 1.953125f;

    // seed tap: only reachable in chunk a (when s == 0, ja <= 12)
    if (ja + 0 == 0) a0 *= 5.0f;   if (ja + 0 > n) a0 = 0.0f;
    if (ja + 1 == 0) a1 *= 5.0f;   if (ja + 1 > n) a1 = 0.0f;
    if (ja + 2 == 0) a2 *= 5.0f;   if (ja + 2 > n) a2 = 0.0f;
    if (ja + 3 == 0) a3 *= 5.0f;   if (ja + 3 > n) a3 = 0.0f;
    if (jb + 0 > n) b0 = 0.0f;
    if (jb + 1 > n) b1 = 0.0f;
    if (jb + 2 > n) b2 = 0.0f;
    if (jb + 3 > n) b3 = 0.0f;
    if (jc + 0 > n) c0 = 0.0f;
    if (jc + 1 > n) c1 = 0.0f;
    if (jc + 2 > n) c2 = 0.0f;
    if (jc + 3 > n) c3 = 0.0f;
    if (jd + 0 > n) d0 = 0.0f;
    if (jd + 1 > n) d1 = 0.0f;
    if (jd + 2 > n) d2 = 0.0f;
    if (jd + 3 > n) d3 = 0.0f;

    float accA = fmaf(a0, a.x, fmaf(a1, a.y, fmaf(a2, a.z, a3 * a.w)));
    float accB = fmaf(b0, b.x, fmaf(b1, b.y, fmaf(b2, b.z, b3 * b.w)));
    float accC = fmaf(c0, c.x, fmaf(c1, c.y, fmaf(c2, c.z, c3 * c.w)));
    float accD = fmaf(d0, d.x, fmaf(d1, d.y, fmaf(d2, d.z, d3 * d.w)));
    float acc = (accA + accB) + (accC + accD);

    // reduce over the 4-lane group (xor offsets stay within the group)
    acc += __shfl_xor_sync(0xffffffffu, acc, 2);
    acc += __shfl_xor_sync(0xffffffffu, acc, 1);

    if (sub == 0) out[row] = acc;
}

extern "C" void kernel_launch(void* const* d_in, const int* in_sizes, int n_in,
                              void* d_out, int out_size)
{
    const float* pop_history = (const float*)d_in[0];
    const int*   valid_len   = (const int*)d_in[1];
    float*       out         = (float*)d_out;

    int B = in_sizes[1];               // 16384
    int T = in_sizes[0] / in_sizes[1]; // 2048

    int threads = 256;                 // 8 warps = 64 rows per block
    int rows_per_block = (threads / 32) * 8;
    int blocks = (B + rows_per_block - 1) / rows_per_block;   // 256
    ema_last_kernel<<<blocks, threads>>>(pop_history, valid_len, out, B, T);
}

// round 15
// speedup vs baseline: 1.0288x; 1.0288x over previous
#include <cuda_runtime.h>

// EMA alpha=0.2; out[i] = e_{idx}, idx = max(len[i],1)-1.
// 64-tap trailing window (tail weight 0.8^63 ~ 8e-7 << 1e-3 threshold);
// rows with idx < 64 computed exactly from x_0.
//
// FINAL (canonical best, R1-R14): 4-lane row groups, 8 rows per warp ->
// 2048 warps, 256 CTAs of 256 threads (16 warps/SM latency-hiding knee;
// 8 w/SM regresses, 32 w/SM ties). Each lane: FOUR independent aligned
// LDG.128 (float4) covering the 64-float window (MLP=4). Window start
// aligned up to 4 (keeps s >= n-63), clamped to [0, T-64]. Tap-mask
// predicates execute in the shadow of the in-flight loads (free).
//
// Measured distribution of THIS exact source across 7 draws:
// bench min 6.62 / median ~6.7 / max 7.14 us; ncu 5.70-6.05 us.
// Overhead-bound floor: launch/ramp ~2.8us + dependent len->window trip
// (mostly L2-hit across graph replays) + drain. DRAM 13%, issue 12% —
// no throughput axis remains; all structural levers swept and noise-equal.

#define LOG2_08  (-0.32192809488736234787f)  // log2(0.8)
#define INV08_16 (35.52713678800501f)        // 0.8^-16 = 1.25^16

__global__ void __launch_bounds__(256)
ema_last_kernel(const float* __restrict__ x,
                const int* __restrict__ valid_len,
                float* __restrict__ out,
                int B, int T)
{
    int warp = (int)((blockIdx.x * blockDim.x + threadIdx.x) >> 5);
    int lane = threadIdx.x & 31;
    int sub  = lane & 3;                 // lane within 4-lane row group
    int row  = warp * 8 + (lane >> 2);
    if (row >= B) return;

    int len = valid_len[row];
    int n   = (len > 1 ? len : 1) - 1;   // target index idx = L-1

    // Aligned window start: s in [n-63, n-60] (or 0), 4-aligned, in-row.
    int s = n - 63;
    s = (s > 0) ? ((s + 3) & ~3) : 0;
    if (s > T - 64) s = T - 64;

    const float4* p = reinterpret_cast<const float4*>(x + (size_t)row * (size_t)T + s);
    // Four independent loads issue back-to-back (MLP=4).
    float4 a = p[sub];
    float4 b = p[sub + 4];
    float4 c = p[sub + 8];
    float4 d = p[sub + 12];

    int ja = s + 4 * sub;                // global index of a.x
    int jb = ja + 16, jc = ja + 32, jd = ja + 48;

    // tap weight: 0.2 * 0.8^(n - j); seed (j==0) coefficient is 0.8^n = 5x that.
    float wa = 0.2f * exp2f((float)(n - ja) * LOG2_08);
    float wb = wa * INV08_16;
    float wc = wb * INV08_16;
    float wd = wc * INV08_16;

    float a0 = wa, a1 = wa * 1.25f, a2 = wa * 1.5625f, a3 = wa * 1.953125f;
    float b0 = wb, b1 = wb * 1.25f, b2 = wb * 1.5625f, b3 = wb * 1.953125f;
    float c0 = wc, c1 = wc * 1.25f, c2 = wc * 1.5625f, c3 = wc * 1.953125f;
    float d0 = wd, d1 = wd * 1.25f, d2 = wd * 1.5625f, d3 = wd * 1.953125f;

    // seed tap: only reachable in chunk a (when s == 0, ja <= 12)
    if (ja + 0 == 0) a0 *= 5.0f;   if (ja + 0 > n) a0 = 0.0f;
    if (ja + 1 == 0) a1 *= 5.0f;   if (ja + 1 > n) a1 = 0.0f;
    if (ja + 2 == 0) a2 *= 5.0f;   if (ja + 2 > n) a2 = 0.0f;
    if (ja + 3 == 0) a3 *= 5.0f;   if (ja + 3 > n) a3 = 0.0f;
    if (jb + 0 > n) b0 = 0.0f;
    if (jb + 1 > n) b1 = 0.0f;
    if (jb + 2 > n) b2 = 0.0f;
    if (jb + 3 > n) b3 = 0.0f;
    if (jc + 0 > n) c0 = 0.0f;
    if (jc + 1 > n) c1 = 0.0f;
    if (jc + 2 > n) c2 = 0.0f;
    if (jc + 3 > n) c3 = 0.0f;
    if (jd + 0 > n) d0 = 0.0f;
    if (jd + 1 > n) d1 = 0.0f;
    if (jd + 2 > n) d2 = 0.0f;
    if (jd + 3 > n) d3 = 0.0f;

    float accA = fmaf(a0, a.x, fmaf(a1, a.y, fmaf(a2, a.z, a3 * a.w)));
    float accB = fmaf(b0, b.x, fmaf(b1, b.y, fmaf(b2, b.z, b3 * b.w)));
    float accC = fmaf(c0, c.x, fmaf(c1, c.y, fmaf(c2, c.z, c3 * c.w)));
    float accD = fmaf(d0, d.x, fmaf(d1, d.y, fmaf(d2, d.z, d3 * d.w)));
    float acc = (accA + accB) + (accC + accD);

    // reduce over the 4-lane group (xor offsets stay within the group)
    acc += __shfl_xor_sync(0xffffffffu, acc, 2);
    acc += __shfl_xor_sync(0xffffffffu, acc, 1);

    if (sub == 0) out[row] = acc;
}

extern "C" void kernel_launch(void* const* d_in, const int* in_sizes, int n_in,
                              void* d_out, int out_size)
{
    const float* pop_history = (const float*)d_in[0];
    const int*   valid_len   = (const int*)d_in[1];
    float*       out         = (float*)d_out;

    int B = in_sizes[1];               // 16384
    int T = in_sizes[0] / in_sizes[1]; // 2048

    int threads = 256;                 // 8 warps = 64 rows per block
    int rows_per_block = (threads / 32) * 8;
    int blocks = (B + rows_per_block - 1) / rows_per_block;   // 256
    ema_last_kernel<<<blocks, threads>>>(pop_history, valid_len, out, B, T);
}

// round 16
// speedup vs baseline: 1.0338x; 1.0048x over previous
#include <cuda_runtime.h>

// EMA alpha=0.2; out[i] = e_{idx}, idx = max(len[i],1)-1.
// 64-tap trailing window (tail weight 0.8^63 ~ 8e-7 << 1e-3 threshold);
// rows with idx < 64 computed exactly from x_0.
//
// FINAL (canonical best, R1-R15): 4-lane row groups, 8 rows per warp ->
// 2048 warps, 256 CTAs of 256 threads (16 warps/SM latency-hiding knee;
// 8 w/SM regresses, 32 w/SM ties). Each lane: FOUR independent aligned
// LDG.128 (float4) covering the 64-float window (MLP=4). Window start
// aligned up to 4 (keeps s >= n-63), clamped to [0, T-64]. Tap-mask
// predicates and exp2f execute in the shadow of the in-flight loads.
//
// Measured distribution of THIS exact source across 8 draws:
// bench {6.62x3, 6.66x2, 6.85x2, 7.14} us; ncu 5.70-6.05 us.
// Overhead-bound floor: launch/ramp ~2.8us + dependent len->window trip
// (mostly L2-hit across graph replays) + drain. DRAM 13%, issue 12% —
// no throughput axis remains; all structural levers swept and noise-equal.

#define LOG2_08  (-0.32192809488736234787f)  // log2(0.8)
#define INV08_16 (35.52713678800501f)        // 0.8^-16 = 1.25^16

__global__ void __launch_bounds__(256)
ema_last_kernel(const float* __restrict__ x,
                const int* __restrict__ valid_len,
                float* __restrict__ out,
                int B, int T)
{
    int warp = (int)((blockIdx.x * blockDim.x + threadIdx.x) >> 5);
    int lane = threadIdx.x & 31;
    int sub  = lane & 3;                 // lane within 4-lane row group
    int row  = warp * 8 + (lane >> 2);
    if (row >= B) return;

    int len = valid_len[row];
    int n   = (len > 1 ? len : 1) - 1;   // target index idx = L-1

    // Aligned window start: s in [n-63, n-60] (or 0), 4-aligned, in-row.
    int s = n - 63;
    s = (s > 0) ? ((s + 3) & ~3) : 0;
    if (s > T - 64) s = T - 64;

    const float4* p = reinterpret_cast<const float4*>(x + (size_t)row * (size_t)T + s);
    // Four independent loads issue back-to-back (MLP=4).
    float4 a = p[sub];
    float4 b = p[sub + 4];
    float4 c = p[sub + 8];
    float4 d = p[sub + 12];

    int ja = s + 4 * sub;                // global index of a.x
    int jb = ja + 16, jc = ja + 32, jd = ja + 48;

    // tap weight: 0.2 * 0.8^(n - j); seed (j==0) coefficient is 0.8^n = 5x that.
    float wa = 0.2f * exp2f((float)(n - ja) * LOG2_08);
    float wb = wa * INV08_16;
    float wc = wb * INV08_16;
    float wd = wc * INV08_16;

    float a0 = wa, a1 = wa * 1.25f, a2 = wa * 1.5625f, a3 = wa * 1.953125f;
    float b0 = wb, b1 = wb * 1.25f, b2 = wb * 1.5625f, b3 = wb * 1.953125f;
    float c0 = wc, c1 = wc * 1.25f, c2 = wc * 1.5625f, c3 = wc * 1.953125f;
    float d0 = wd, d1 = wd * 1.25f, d2 = wd * 1.5625f, d3 = wd * 1.953125f;

    // seed tap: only reachable in chunk a (when s == 0, ja <= 12)
    if (ja + 0 == 0) a0 *= 5.0f;   if (ja + 0 > n) a0 = 0.0f;
    if (ja + 1 == 0) a1 *= 5.0f;   if (ja + 1 > n) a1 = 0.0f;
    if (ja + 2 == 0) a2 *= 5.0f;   if (ja + 2 > n) a2 = 0.0f;
    if (ja + 3 == 0) a3 *= 5.0f;   if (ja + 3 > n) a3 = 0.0f;
    if (jb + 0 > n) b0 = 0.0f;
    if (jb + 1 > n) b1 = 0.0f;
    if (jb + 2 > n) b2 = 0.0f;
    if (jb + 3 > n) b3 = 0.0f;
    if (jc + 0 > n) c0 = 0.0f;
    if (jc + 1 > n) c1 = 0.0f;
    if (jc + 2 > n) c2 = 0.0f;
    if (jc + 3 > n) c3 = 0.0f;
    if (jd + 0 > n) d0 = 0.0f;
    if (jd + 1 > n) d1 = 0.0f;
    if (jd + 2 > n) d2 = 0.0f;
    if (jd + 3 > n) d3 = 0.0f;

    float accA = fmaf(a0, a.x, fmaf(a1, a.y, fmaf(a2, a.z, a3 * a.w)));
    float accB = fmaf(b0, b.x, fmaf(b1, b.y, fmaf(b2, b.z, b3 * b.w)));
    float accC = fmaf(c0, c.x, fmaf(c1, c.y, fmaf(c2, c.z, c3 * c.w)));
    float accD = fmaf(d0, d.x, fmaf(d1, d.y, fmaf(d2, d.z, d3 * d.w)));
    float acc = (accA + accB) + (accC + accD);

    // reduce over the 4-lane group (xor offsets stay within the group)
    acc += __shfl_xor_sync(0xffffffffu, acc, 2);
    acc += __shfl_xor_sync(0xffffffffu, acc, 1);

    if (sub == 0) out[row] = acc;
}

extern "C" void kernel_launch(void* const* d_in, const int* in_sizes, int n_in,
                              void* d_out, int out_size)
{
    const float* pop_history = (const float*)d_in[0];
    const int*   valid_len   = (const int*)d_in[1];
    float*       out         = (float*)d_out;

    int B = in_sizes[1];               // 16384
    int T = in_sizes[0] / in_sizes[1]; // 2048

    int threads = 256;                 // 8 warps = 64 rows per block
    int rows_per_block = (threads / 32) * 8;
    int blocks = (B + rows_per_block - 1) / rows_per_block;   // 256
    ema_last_kernel<<<blocks, threads>>>(pop_history, valid_len, out, B, T);
}